// round 14
// baseline (speedup 1.0000x reference)
#include <cuda_runtime.h>

#define NE 16
#define NK 4
#define NH 2048
#define NF 4096
#define NT 64
#define JA 8
#define JB 8

typedef unsigned long long u64;

__device__ float g_act[(size_t)NE * NT * NF];   // 16.8 MB scratch
__device__ int   g_cnt[NE];
__device__ int   g_tok[NE * NT];
__device__ float g_rw [NE * NT];

__device__ __forceinline__ u64 pk2(float lo, float hi) {
    u64 r; asm("mov.b64 %0,{%1,%2};" : "=l"(r) : "f"(lo), "f"(hi)); return r;
}
__device__ __forceinline__ void upk2(u64 v, float &lo, float &hi) {
    asm("mov.b64 {%0,%1},%2;" : "=f"(lo), "=f"(hi) : "l"(v));
}
__device__ __forceinline__ void fma2(u64 &d, u64 a, u64 b) {
    asm("fma.rn.f32x2 %0,%1,%2,%0;" : "+l"(d) : "l"(a), "l"(b));
}
__device__ __forceinline__ u64 add2(u64 a, u64 b) {
    u64 r; asm("add.rn.f32x2 %0,%1,%2;" : "=l"(r) : "l"(a), "l"(b)); return r;
}
__device__ __forceinline__ void red4(float* p, float a, float b, float c, float d) {
    asm volatile("red.global.add.v4.f32 [%0], {%1,%2,%3,%4};"
                 :: "l"(p), "f"(a), "f"(b), "f"(c), "f"(d) : "memory");
}
// Dual reduction: lane 0 ends with full sum of a, lane 16 with full sum of b.
__device__ __forceinline__ u64 reduce_pair(u64 a, u64 b, int lane) {
    u64 af = add2(a, __shfl_xor_sync(0xffffffffu, a, 16));
    u64 bf = add2(b, __shfl_xor_sync(0xffffffffu, b, 16));
    u64 m = (lane & 16) ? bf : af;
#pragma unroll
    for (int o = 8; o; o >>= 1)
        m = add2(m, __shfl_xor_sync(0xffffffffu, m, o));
    return m;
}

// ---------------------------------------------------------------------------
// Setup: block 0 builds routing tables; all blocks zero the output.
// ---------------------------------------------------------------------------
__global__ void setup_kernel(const int* __restrict__ tope,
                             const float* __restrict__ topw,
                             float* __restrict__ out)
{
    const int gid = blockIdx.x * blockDim.x + threadIdx.x;
    float4 z = make_float4(0.f, 0.f, 0.f, 0.f);
    float4* o4 = (float4*)out;
    for (int i = gid; i < (NT * NH) / 4; i += gridDim.x * blockDim.x) o4[i] = z;

    if (blockIdx.x == 0) {
        __shared__ int   se[NT * NK];
        __shared__ float sw[NT * NK];
        const int tid = threadIdx.x;
        if (tid < NT * NK) { se[tid] = tope[tid]; sw[tid] = topw[tid]; }
        __syncthreads();
        if (tid < NE) {
            const int e = tid; int c = 0;
            for (int t = 0; t < NT; t++) {
                float r = 0.f; int hit = 0;
#pragma unroll
                for (int k = 0; k < NK; k++)
                    if (se[t * NK + k] == e) { r += sw[t * NK + k]; hit = 1; }
                if (hit) { g_tok[e * NT + c] = t; g_rw[e * NT + c] = r; c++; }
            }
            g_cnt[e] = c;
        }
    }
}

// ---------------------------------------------------------------------------
// Stage A v11: warp owns FOUR f-rows of both w1 and v1 (8 streams). Each
// x LDS.128 feeds 16 FFMA2 -> L1-wf : fma-cyc ratio = 1.0 (was 1.5).
// h-paired f32x2 accs (zero packing MOVs): 8 arrays x JT u64 = 128 regs at
// JT=8. D=2 ring on all 8 streams. (256,1): ~210 regs, 8 warps/SM.
// ---------------------------------------------------------------------------
template<int JT>
__device__ __forceinline__ void stageA_body(
    const float* __restrict__ w1, const float* __restrict__ v1,
    const ulonglong2* xs2, const float* srw, int e, int fbase, int jbase, int J)
{
    const int tid = threadIdx.x, warp = tid >> 5, lane = tid & 31;

#pragma unroll 1
    for (int pass = 0; pass < 2; pass++) {
        const int f0 = fbase + pass * 32 + warp * 4;
        const ulonglong2* pw0 = (const ulonglong2*)(w1 + ((size_t)e * NF + f0) * NH);
        const ulonglong2* pw1 = pw0 + 512;
        const ulonglong2* pw2 = pw0 + 1024;
        const ulonglong2* pw3 = pw0 + 1536;
        const ulonglong2* pv0 = (const ulonglong2*)(v1 + ((size_t)e * NF + f0) * NH);
        const ulonglong2* pv1 = pv0 + 512;
        const ulonglong2* pv2 = pv0 + 1024;
        const ulonglong2* pv3 = pv0 + 1536;

        u64 gw0[JT], gw1[JT], gw2[JT], gw3[JT];
        u64 gv0[JT], gv1[JT], gv2[JT], gv3[JT];
#pragma unroll
        for (int j = 0; j < JT; j++) {
            gw0[j] = 0ull; gw1[j] = 0ull; gw2[j] = 0ull; gw3[j] = 0ull;
            gv0[j] = 0ull; gv1[j] = 0ull; gv2[j] = 0ull; gv3[j] = 0ull;
        }

        ulonglong2 rw0[2], rw1[2], rw2[2], rw3[2];
        ulonglong2 rv0[2], rv1[2], rv2[2], rv3[2];
#pragma unroll
        for (int s = 0; s < 2; s++) {
            const int q = s * 32 + lane;
            rw0[s] = __ldg(pw0 + q); rw1[s] = __ldg(pw1 + q);
            rw2[s] = __ldg(pw2 + q); rw3[s] = __ldg(pw3 + q);
            rv0[s] = __ldg(pv0 + q); rv1[s] = __ldg(pv1 + q);
            rv2[s] = __ldg(pv2 + q); rv3[s] = __ldg(pv3 + q);
        }

#pragma unroll 2
        for (int c = 0; c < 16; c++) {
            const int sl = c & 1;
            const int qb = c * 32 + lane;
#pragma unroll
            for (int j = 0; j < JT; j++) {
                const ulonglong2 xv = xs2[j * 512 + qb];   // one LDS.128, 16 FFMA2
                fma2(gw0[j], rw0[sl].x, xv.x); fma2(gw0[j], rw0[sl].y, xv.y);
                fma2(gw1[j], rw1[sl].x, xv.x); fma2(gw1[j], rw1[sl].y, xv.y);
                fma2(gw2[j], rw2[sl].x, xv.x); fma2(gw2[j], rw2[sl].y, xv.y);
                fma2(gw3[j], rw3[sl].x, xv.x); fma2(gw3[j], rw3[sl].y, xv.y);
                fma2(gv0[j], rv0[sl].x, xv.x); fma2(gv0[j], rv0[sl].y, xv.y);
                fma2(gv1[j], rv1[sl].x, xv.x); fma2(gv1[j], rv1[sl].y, xv.y);
                fma2(gv2[j], rv2[sl].x, xv.x); fma2(gv2[j], rv2[sl].y, xv.y);
                fma2(gv3[j], rv3[sl].x, xv.x); fma2(gv3[j], rv3[sl].y, xv.y);
            }
            if (c < 14) {
                const int q = (c + 2) * 32 + lane;
                rw0[sl] = __ldg(pw0 + q); rw1[sl] = __ldg(pw1 + q);
                rw2[sl] = __ldg(pw2 + q); rw3[sl] = __ldg(pw3 + q);
                rv0[sl] = __ldg(pv0 + q); rv1[sl] = __ldg(pv1 + q);
                rv2[sl] = __ldg(pv2 + q); rv3[sl] = __ldg(pv3 + q);
            }
        }

#pragma unroll
        for (int j = 0; j < JT; j++) {
            const u64 wA = reduce_pair(gw0[j], gw1[j], lane);  // lane0: f0, lane16: f0+1
            const u64 wB = reduce_pair(gw2[j], gw3[j], lane);  // lane0: f0+2, lane16: f0+3
            const u64 vA = reduce_pair(gv0[j], gv1[j], lane);
            const u64 vB = reduce_pair(gv2[j], gv3[j], lane);
            if ((lane & 15) == 0 && j < J) {
                const int r = lane >> 4;
                const float rwj = srw[j];
                float a, b;
                upk2(wA, a, b); const float gA = a + b;
                upk2(vA, a, b); const float uA = a + b;
                const float sA = gA / (1.f + __expf(-gA));
                g_act[((size_t)(e * NT + jbase + j)) * NF + f0 + r] = sA * uA * rwj;
                upk2(wB, a, b); const float gB = a + b;
                upk2(vB, a, b); const float uB = a + b;
                const float sB = gB / (1.f + __expf(-gB));
                g_act[((size_t)(e * NT + jbase + j)) * NF + f0 + 2 + r] = sB * uB * rwj;
            }
        }
    }
}

__global__ void __launch_bounds__(256, 1) stageA_kernel(
    const float* __restrict__ x, const float* __restrict__ w1, const float* __restrict__ v1)
{
    const int e = blockIdx.y;
    const int ftile = blockIdx.x >> 3, chunk = blockIdx.x & 7;  // chunk fastest: L2 dedup
    const int jbase = chunk * JA;
    const int cnt = g_cnt[e];
    if (jbase >= cnt) return;
    const int J  = min(JA, cnt - jbase);
    const int Jp = ((J + 3) >> 2) << 2;

    extern __shared__ __align__(16) float xs[];
    __shared__ int   stok[JA];
    __shared__ float srw [JA];
    const int tid = threadIdx.x;
    if (tid < JA) {
        stok[tid] = (tid < J) ? g_tok[e * NT + jbase + tid] : 0;
        srw [tid] = (tid < J) ? g_rw [e * NT + jbase + tid] : 0.f;
    }
    __syncthreads();

    float4* xs4 = (float4*)xs;
    const float4* x4 = (const float4*)x;
    for (int idx = tid; idx < Jp * 512; idx += 256) {
        const int j = idx >> 9, q = idx & 511;
        xs4[idx] = (j < J) ? __ldg(x4 + (size_t)stok[j] * 512 + q)
                           : make_float4(0.f, 0.f, 0.f, 0.f);
    }
    __syncthreads();

    const int fbase = ftile * 64;
    if (((J + 3) >> 2) == 1)
        stageA_body<4>(w1, v1, (const ulonglong2*)xs, srw, e, fbase, jbase, J);
    else
        stageA_body<8>(w1, v1, (const ulonglong2*)xs, srw, e, fbase, jbase, J);
}

// ---------------------------------------------------------------------------
// Stage B (unchanged): thread owns 4 h, 3 CTAs/SM, broadcast LDS.64 + pk2.
// ---------------------------------------------------------------------------
template<int JT>
__device__ __forceinline__ void stageB_body(
    const float* __restrict__ w2, float* __restrict__ out,
    const float* sact, const int* stok, int e, int f0, int h0, int J)
{
    const int tid = threadIdx.x;                 // 256 threads, h = h0 + tid*4
    u64 A0[JT], A1[JT];
#pragma unroll
    for (int j = 0; j < JT; j++) { A0[j] = 0ull; A1[j] = 0ull; }

    const ulonglong2* wq = (const ulonglong2*)(w2 + ((size_t)e * NF + f0) * NH)
                           + (h0 >> 2) + tid;

    ulonglong2 Ra[2], Rb[2];                     // [slot]: rows 2s and 2s+1
    Ra[0] = __ldg(wq);        Rb[0] = __ldg(wq + 512);
    Ra[1] = __ldg(wq + 1024); Rb[1] = __ldg(wq + 1536);

#pragma unroll 2
    for (int s = 0; s < 128; s++) {
        const int sl = s & 1;
#pragma unroll
        for (int j = 0; j < JT; j++) {
            const float2 a2 = *(const float2*)(sact + j * 256 + 2 * s); // LDS.64 bcast
            const u64 dx = pk2(a2.x, a2.x);
            const u64 dy = pk2(a2.y, a2.y);
            fma2(A0[j], Ra[sl].x, dx); fma2(A1[j], Ra[sl].y, dx);
            fma2(A0[j], Rb[sl].x, dy); fma2(A1[j], Rb[sl].y, dy);
        }
        if (s < 126) {
            const ulonglong2* np = wq + (size_t)(2 * (s + 2)) * 512;
            Ra[sl] = __ldg(np);
            Rb[sl] = __ldg(np + 512);
        }
    }

#pragma unroll
    for (int j = 0; j < JT; j++) {
        if (j < J) {
            float a0, a1, a2, a3;
            upk2(A0[j], a0, a1); upk2(A1[j], a2, a3);
            red4(out + (size_t)stok[j] * NH + h0 + tid * 4, a0, a1, a2, a3);
        }
    }
}

__global__ void __launch_bounds__(256, 3) stageB_kernel(
    const float* __restrict__ w2, float* __restrict__ out)
{
    const int jc = blockIdx.x, e = blockIdx.y;            // jc fastest: L2 dedup on w2
    const int fs = blockIdx.z >> 1, hh = blockIdx.z & 1;
    const int jbase = jc * JB;
    const int cnt = g_cnt[e];
    if (jbase >= cnt) return;
    const int J  = min(JB, cnt - jbase);
    const int Jp = ((J + 3) >> 2) << 2;
    const int f0 = fs * 256, h0 = hh * 1024;

    extern __shared__ __align__(16) float sact[];         // [JB][256] plain act
    __shared__ int stok[JB];
    const int tid = threadIdx.x;
    if (tid < JB) stok[tid] = (tid < J) ? g_tok[e * NT + jbase + tid] : 0;
    __syncthreads();

    for (int idx = tid; idx < Jp * 256; idx += 256) {
        const int j = idx >> 8, q = idx & 255;
        sact[idx] = (j < J)
            ? g_act[((size_t)(e * NT + jbase + j)) * NF + f0 + q] : 0.f;
    }
    __syncthreads();

    if (((J + 3) >> 2) == 1)
        stageB_body<4>(w2, out, sact, stok, e, f0, h0, J);
    else
        stageB_body<8>(w2, out, sact, stok, e, f0, h0, J);
}

// ---------------------------------------------------------------------------
extern "C" void kernel_launch(void* const* d_in, const int* in_sizes, int n_in,
                              void* d_out, int out_size)
{
    const float* x    = (const float*)d_in[0];
    const float* topw = (const float*)d_in[2];
    const int*   tope = (const int*)  d_in[3];
    const float* w1   = (const float*)d_in[4];
    const float* v1   = (const float*)d_in[5];
    const float* w2   = (const float*)d_in[6];
    float* out = (float*)d_out;

    cudaFuncSetAttribute(stageA_kernel, cudaFuncAttributeMaxDynamicSharedMemorySize, JA * NH * 4);
    cudaFuncSetAttribute(stageB_kernel, cudaFuncAttributeMaxDynamicSharedMemorySize, JB * 256 * 4);

    setup_kernel<<<64, 256>>>(tope, topw, out);
    stageA_kernel<<<dim3(512, NE), 256, JA * NH * 4>>>(x, w1, v1);
    stageB_kernel<<<dim3(8, NE, 32), 256, JB * 256 * 4>>>(w2, out);
}

// round 15
// speedup vs baseline: 1.1371x; 1.1371x over previous
#include <cuda_runtime.h>

#define NE 16
#define NK 4
#define NH 2048
#define NF 4096
#define NT 64
#define JA 8
#define JB 8

typedef unsigned long long u64;

__device__ float g_act[(size_t)NE * NT * NF];   // 16.8 MB scratch
__device__ int   g_cnt[NE];
__device__ int   g_tok[NE * NT];
__device__ float g_rw [NE * NT];

__device__ __forceinline__ u64 pk2(float lo, float hi) {
    u64 r; asm("mov.b64 %0,{%1,%2};" : "=l"(r) : "f"(lo), "f"(hi)); return r;
}
__device__ __forceinline__ void upk2(u64 v, float &lo, float &hi) {
    asm("mov.b64 {%0,%1},%2;" : "=f"(lo), "=f"(hi) : "l"(v));
}
__device__ __forceinline__ void fma2(u64 &d, u64 a, u64 b) {
    asm("fma.rn.f32x2 %0,%1,%2,%0;" : "+l"(d) : "l"(a), "l"(b));
}
__device__ __forceinline__ u64 add2(u64 a, u64 b) {
    u64 r; asm("add.rn.f32x2 %0,%1,%2;" : "=l"(r) : "l"(a), "l"(b)); return r;
}
__device__ __forceinline__ void red4(float* p, float a, float b, float c, float d) {
    asm volatile("red.global.add.v4.f32 [%0], {%1,%2,%3,%4};"
                 :: "l"(p), "f"(a), "f"(b), "f"(c), "f"(d) : "memory");
}
// Dual reduction: lane 0 ends with full sum of a, lane 16 with full sum of b.
__device__ __forceinline__ u64 reduce_pair(u64 a, u64 b, int lane) {
    u64 af = add2(a, __shfl_xor_sync(0xffffffffu, a, 16));
    u64 bf = add2(b, __shfl_xor_sync(0xffffffffu, b, 16));
    u64 m = (lane & 16) ? bf : af;
#pragma unroll
    for (int o = 8; o; o >>= 1)
        m = add2(m, __shfl_xor_sync(0xffffffffu, m, o));
    return m;
}

// ---------------------------------------------------------------------------
// Setup: block 0 builds routing tables; all blocks zero the output.
// ---------------------------------------------------------------------------
__global__ void setup_kernel(const int* __restrict__ tope,
                             const float* __restrict__ topw,
                             float* __restrict__ out)
{
    const int gid = blockIdx.x * blockDim.x + threadIdx.x;
    float4 z = make_float4(0.f, 0.f, 0.f, 0.f);
    float4* o4 = (float4*)out;
    for (int i = gid; i < (NT * NH) / 4; i += gridDim.x * blockDim.x) o4[i] = z;

    if (blockIdx.x == 0) {
        __shared__ int   se[NT * NK];
        __shared__ float sw[NT * NK];
        const int tid = threadIdx.x;
        if (tid < NT * NK) { se[tid] = tope[tid]; sw[tid] = topw[tid]; }
        __syncthreads();
        if (tid < NE) {
            const int e = tid; int c = 0;
            for (int t = 0; t < NT; t++) {
                float r = 0.f; int hit = 0;
#pragma unroll
                for (int k = 0; k < NK; k++)
                    if (se[t * NK + k] == e) { r += sw[t * NK + k]; hit = 1; }
                if (hit) { g_tok[e * NT + c] = t; g_rw[e * NT + c] = r; c++; }
            }
            g_cnt[e] = c;
        }
    }
}

// ---------------------------------------------------------------------------
// Stage A (R10 winner, verbatim): token-paired f32x2 accumulators, x staged
// pre-interleaved as (x_j0[h], x_j1[h]) u64 pairs, D=3 LDG ring, 2 CTAs/SM.
// ---------------------------------------------------------------------------
template<int JP>   // number of token pairs (1..4)
__device__ __forceinline__ void stageA_body(
    const float* __restrict__ w1, const float* __restrict__ v1,
    const u64* xq, const float* srw, int e, int fbase, int jbase, int J)
{
    const int tid = threadIdx.x, warp = tid >> 5, lane = tid & 31;
    const ulonglong2* xq2 = (const ulonglong2*)xq;

#pragma unroll 1
    for (int pass = 0; pass < 4; pass++) {
        const int f0 = fbase + pass * 16 + warp * 2;
        const ulonglong2* pwa = (const ulonglong2*)(w1 + ((size_t)e * NF + f0) * NH);
        const ulonglong2* pwb = pwa + 512;
        const ulonglong2* pva = (const ulonglong2*)(v1 + ((size_t)e * NF + f0) * NH);
        const ulonglong2* pvb = pva + 512;

        u64 aW0[JP], aW1[JP], aV0[JP], aV1[JP];
#pragma unroll
        for (int p = 0; p < JP; p++) { aW0[p] = 0ull; aW1[p] = 0ull; aV0[p] = 0ull; aV1[p] = 0ull; }

        ulonglong2 rwa[3], rwb[3], rva[3], rvb[3];
#pragma unroll
        for (int s = 0; s < 3; s++) {
            const int q = s * 32 + lane;
            rwa[s] = __ldg(pwa + q); rwb[s] = __ldg(pwb + q);
            rva[s] = __ldg(pva + q); rvb[s] = __ldg(pvb + q);
        }

#pragma unroll 3
        for (int c = 0; c < 15; c++) {
            const int sl = c % 3;
            float t0, t1, t2, t3;
            upk2(rwa[sl].x, t0, t1); upk2(rwa[sl].y, t2, t3);
            const u64 dwa0 = pk2(t0, t0), dwa1 = pk2(t1, t1), dwa2 = pk2(t2, t2), dwa3 = pk2(t3, t3);
            upk2(rwb[sl].x, t0, t1); upk2(rwb[sl].y, t2, t3);
            const u64 dwb0 = pk2(t0, t0), dwb1 = pk2(t1, t1), dwb2 = pk2(t2, t2), dwb3 = pk2(t3, t3);
            upk2(rva[sl].x, t0, t1); upk2(rva[sl].y, t2, t3);
            const u64 dva0 = pk2(t0, t0), dva1 = pk2(t1, t1), dva2 = pk2(t2, t2), dva3 = pk2(t3, t3);
            upk2(rvb[sl].x, t0, t1); upk2(rvb[sl].y, t2, t3);
            const u64 dvb0 = pk2(t0, t0), dvb1 = pk2(t1, t1), dvb2 = pk2(t2, t2), dvb3 = pk2(t3, t3);

#pragma unroll
            for (int p = 0; p < JP; p++) {
                const ulonglong2 xv0 = xq2[p * 1024 + c * 64 + lane];
                const ulonglong2 xv1 = xq2[p * 1024 + c * 64 + 32 + lane];
                fma2(aW0[p], dwa0, xv0.x); fma2(aW0[p], dwa1, xv0.y);
                fma2(aW0[p], dwa2, xv1.x); fma2(aW0[p], dwa3, xv1.y);
                fma2(aW1[p], dwb0, xv0.x); fma2(aW1[p], dwb1, xv0.y);
                fma2(aW1[p], dwb2, xv1.x); fma2(aW1[p], dwb3, xv1.y);
                fma2(aV0[p], dva0, xv0.x); fma2(aV0[p], dva1, xv0.y);
                fma2(aV0[p], dva2, xv1.x); fma2(aV0[p], dva3, xv1.y);
                fma2(aV1[p], dvb0, xv0.x); fma2(aV1[p], dvb1, xv0.y);
                fma2(aV1[p], dvb2, xv1.x); fma2(aV1[p], dvb3, xv1.y);
            }
            if (c < 13) {
                const int q = (c + 3) * 32 + lane;
                rwa[sl] = __ldg(pwa + q); rwb[sl] = __ldg(pwb + q);
                rva[sl] = __ldg(pva + q); rvb[sl] = __ldg(pvb + q);
            }
        }
        {   // final step c = 15, slot 0
            const int c = 15, sl = 0;
            float t0, t1, t2, t3;
            upk2(rwa[sl].x, t0, t1); upk2(rwa[sl].y, t2, t3);
            const u64 dwa0 = pk2(t0, t0), dwa1 = pk2(t1, t1), dwa2 = pk2(t2, t2), dwa3 = pk2(t3, t3);
            upk2(rwb[sl].x, t0, t1); upk2(rwb[sl].y, t2, t3);
            const u64 dwb0 = pk2(t0, t0), dwb1 = pk2(t1, t1), dwb2 = pk2(t2, t2), dwb3 = pk2(t3, t3);
            upk2(rva[sl].x, t0, t1); upk2(rva[sl].y, t2, t3);
            const u64 dva0 = pk2(t0, t0), dva1 = pk2(t1, t1), dva2 = pk2(t2, t2), dva3 = pk2(t3, t3);
            upk2(rvb[sl].x, t0, t1); upk2(rvb[sl].y, t2, t3);
            const u64 dvb0 = pk2(t0, t0), dvb1 = pk2(t1, t1), dvb2 = pk2(t2, t2), dvb3 = pk2(t3, t3);
#pragma unroll
            for (int p = 0; p < JP; p++) {
                const ulonglong2 xv0 = xq2[p * 1024 + c * 64 + lane];
                const ulonglong2 xv1 = xq2[p * 1024 + c * 64 + 32 + lane];
                fma2(aW0[p], dwa0, xv0.x); fma2(aW0[p], dwa1, xv0.y);
                fma2(aW0[p], dwa2, xv1.x); fma2(aW0[p], dwa3, xv1.y);
                fma2(aW1[p], dwb0, xv0.x); fma2(aW1[p], dwb1, xv0.y);
                fma2(aW1[p], dwb2, xv1.x); fma2(aW1[p], dwb3, xv1.y);
                fma2(aV0[p], dva0, xv0.x); fma2(aV0[p], dva1, xv0.y);
                fma2(aV0[p], dva2, xv1.x); fma2(aV0[p], dva3, xv1.y);
                fma2(aV1[p], dvb0, xv0.x); fma2(aV1[p], dvb1, xv0.y);
                fma2(aV1[p], dvb2, xv1.x); fma2(aV1[p], dvb3, xv1.y);
            }
        }

#pragma unroll
        for (int p = 0; p < JP; p++) {
            const u64 rg = reduce_pair(aW0[p], aW1[p], lane);
            const u64 ru = reduce_pair(aV0[p], aV1[p], lane);
            if ((lane & 15) == 0) {
                float g0, g1, u0, u1;
                upk2(rg, g0, g1); upk2(ru, u0, u1);
                const int f = f0 + (lane >> 4);
                const int j0 = 2 * p, j1 = 2 * p + 1;
                if (j0 < J) {
                    const float s = g0 / (1.f + __expf(-g0));
                    g_act[((size_t)(e * NT + jbase + j0)) * NF + f] = s * u0 * srw[j0];
                }
                if (j1 < J) {
                    const float s = g1 / (1.f + __expf(-g1));
                    g_act[((size_t)(e * NT + jbase + j1)) * NF + f] = s * u1 * srw[j1];
                }
            }
        }
    }
}

__global__ void __launch_bounds__(256, 2) stageA_kernel(
    const float* __restrict__ x, const float* __restrict__ w1, const float* __restrict__ v1)
{
    const int e = blockIdx.y;
    const int ftile = blockIdx.x >> 3, chunk = blockIdx.x & 7;
    const int jbase = chunk * JA;
    const int cnt = g_cnt[e];
    if (jbase >= cnt) return;
    const int J  = min(JA, cnt - jbase);
    const int JP = (J + 1) >> 1;

    extern __shared__ __align__(16) u64 xq[];
    __shared__ int   stok[JA];
    __shared__ float srw [JA];
    const int tid = threadIdx.x;
    if (tid < JA) {
        stok[tid] = (tid < J) ? g_tok[e * NT + jbase + tid] : 0;
        srw [tid] = (tid < J) ? g_rw [e * NT + jbase + tid] : 0.f;
    }
    __syncthreads();

    const float4* x4 = (const float4*)x;
    for (int idx = tid; idx < JP * 512; idx += 256) {
        const int jp = idx >> 9, q4 = idx & 511;
        const float4 xa = __ldg(x4 + (size_t)stok[2 * jp] * 512 + q4);
        const float4 xb = __ldg(x4 + (size_t)stok[2 * jp + 1] * 512 + q4);
        const int c = q4 >> 5, l5 = q4 & 31;
        ulonglong2* d0 = (ulonglong2*)(xq + jp * 2048 + c * 128 + l5 * 2);
        ulonglong2* d1 = (ulonglong2*)(xq + jp * 2048 + c * 128 + 64 + l5 * 2);
        *d0 = make_ulonglong2(pk2(xa.x, xb.x), pk2(xa.y, xb.y));
        *d1 = make_ulonglong2(pk2(xa.z, xb.z), pk2(xa.w, xb.w));
    }
    __syncthreads();

    const int fbase = ftile * 64;
    switch (JP) {
        case 1:  stageA_body<1>(w1, v1, xq, srw, e, fbase, jbase, J); break;
        case 2:  stageA_body<2>(w1, v1, xq, srw, e, fbase, jbase, J); break;
        case 3:  stageA_body<3>(w1, v1, xq, srw, e, fbase, jbase, J); break;
        default: stageA_body<4>(w1, v1, xq, srw, e, fbase, jbase, J); break;
    }
}

// ---------------------------------------------------------------------------
// Stage B v3: token-paired accumulators. acc u64 = (out_j0[h], out_j1[h]);
// act staged in smem pre-packed (a_j0[f], a_j1[f]). Thread owns 8 h.
// Per f-step: 2 LDG.128 + JP LDS.64 + 12 dup-MOV + 8*JP FFMA2 -> wf ratio ~1.0.
// ---------------------------------------------------------------------------
template<int JP>
__device__ __forceinline__ void stageB_body(
    const float* __restrict__ w2, float* __restrict__ out,
    const u64* spair, const int* stok, int e, int f0, int J)
{
    const int tid = threadIdx.x;                 // 256 threads, h = tid*8
    u64 A[JP][8];
#pragma unroll
    for (int p = 0; p < JP; p++)
#pragma unroll
        for (int k = 0; k < 8; k++) A[p][k] = 0ull;

    const ulonglong2* wq = (const ulonglong2*)(w2 + ((size_t)e * NF + f0) * NH) + tid * 2;

    ulonglong2 Ra[2], Rb[2];                     // [slot]: h0..3, h4..7 of row s
    Ra[0] = __ldg(wq);       Rb[0] = __ldg(wq + 1);
    Ra[1] = __ldg(wq + 512); Rb[1] = __ldg(wq + 513);

#pragma unroll 2
    for (int s = 0; s < 256; s++) {
        const int sl = s & 1;
        float t0, t1, t2, t3;
        upk2(Ra[sl].x, t0, t1); upk2(Ra[sl].y, t2, t3);
        const u64 dw0 = pk2(t0, t0), dw1 = pk2(t1, t1), dw2 = pk2(t2, t2), dw3 = pk2(t3, t3);
        upk2(Rb[sl].x, t0, t1); upk2(Rb[sl].y, t2, t3);
        const u64 dw4 = pk2(t0, t0), dw5 = pk2(t1, t1), dw6 = pk2(t2, t2), dw7 = pk2(t3, t3);
#pragma unroll
        for (int p = 0; p < JP; p++) {
            const u64 ap = spair[p * 256 + s];   // LDS.64 broadcast: (a_j0, a_j1)
            fma2(A[p][0], dw0, ap); fma2(A[p][1], dw1, ap);
            fma2(A[p][2], dw2, ap); fma2(A[p][3], dw3, ap);
            fma2(A[p][4], dw4, ap); fma2(A[p][5], dw5, ap);
            fma2(A[p][6], dw6, ap); fma2(A[p][7], dw7, ap);
        }
        if (s < 254) {
            const ulonglong2* np = wq + (size_t)(s + 2) * 512;
            Ra[sl] = __ldg(np);
            Rb[sl] = __ldg(np + 1);
        }
    }

#pragma unroll
    for (int p = 0; p < JP; p++) {
        float lo[8], hi[8];
#pragma unroll
        for (int k = 0; k < 8; k++) upk2(A[p][k], lo[k], hi[k]);
        const int j0 = 2 * p, j1 = 2 * p + 1;
        if (j0 < J) {
            float* op = out + (size_t)stok[j0] * NH + tid * 8;
            red4(op,     lo[0], lo[1], lo[2], lo[3]);
            red4(op + 4, lo[4], lo[5], lo[6], lo[7]);
        }
        if (j1 < J) {
            float* op = out + (size_t)stok[j1] * NH + tid * 8;
            red4(op,     hi[0], hi[1], hi[2], hi[3]);
            red4(op + 4, hi[4], hi[5], hi[6], hi[7]);
        }
    }
}

__global__ void __launch_bounds__(256, 2) stageB_kernel(
    const float* __restrict__ w2, float* __restrict__ out)
{
    const int jc = blockIdx.x, e = blockIdx.y;            // jc fastest: L2 dedup on w2
    const int jbase = jc * JB;
    const int cnt = g_cnt[e];
    if (jbase >= cnt) return;
    const int J  = min(JB, cnt - jbase);
    const int JP = (J + 1) >> 1;
    const int f0 = blockIdx.z * 256;

    extern __shared__ __align__(16) u64 spair[];          // [JP][256] packed act pairs
    __shared__ int stok[JB];
    const int tid = threadIdx.x;
    if (tid < JB) stok[tid] = (tid < J) ? g_tok[e * NT + jbase + tid] : 0;
    __syncthreads();

    for (int idx = tid; idx < JP * 256; idx += 256) {
        const int p = idx >> 8, q = idx & 255;
        const int j0 = 2 * p, j1 = 2 * p + 1;
        const float a0 = (j0 < J)
            ? g_act[((size_t)(e * NT + jbase + j0)) * NF + f0 + q] : 0.f;
        const float a1 = (j1 < J)
            ? g_act[((size_t)(e * NT + jbase + j1)) * NF + f0 + q] : 0.f;
        spair[idx] = pk2(a0, a1);
    }
    __syncthreads();

    switch (JP) {
        case 1:  stageB_body<1>(w2, out, spair, stok, e, f0, J); break;
        case 2:  stageB_body<2>(w2, out, spair, stok, e, f0, J); break;
        case 3:  stageB_body<3>(w2, out, spair, stok, e, f0, J); break;
        default: stageB_body<4>(w2, out, spair, stok, e, f0, J); break;
    }
}

// ---------------------------------------------------------------------------
extern "C" void kernel_launch(void* const* d_in, const int* in_sizes, int n_in,
                              void* d_out, int out_size)
{
    const float* x    = (const float*)d_in[0];
    const float* topw = (const float*)d_in[2];
    const int*   tope = (const int*)  d_in[3];
    const float* w1   = (const float*)d_in[4];
    const float* v1   = (const float*)d_in[5];
    const float* w2   = (const float*)d_in[6];
    float* out = (float*)d_out;

    cudaFuncSetAttribute(stageA_kernel, cudaFuncAttributeMaxDynamicSharedMemorySize, 4 * 2048 * 8);
    cudaFuncSetAttribute(stageB_kernel, cudaFuncAttributeMaxDynamicSharedMemorySize, 4 * 256 * 8);

    setup_kernel<<<64, 256>>>(tope, topw, out);
    stageA_kernel<<<dim3(512, NE), 256, 4 * 2048 * 8>>>(x, w1, v1);
    stageB_kernel<<<dim3(8, NE, 16), 256, 4 * 256 * 8>>>(w2, out);
}

// round 16
// speedup vs baseline: 1.3003x; 1.1436x over previous
#include <cuda_runtime.h>

#define NE 16
#define NK 4
#define NH 2048
#define NF 4096
#define NT 64
#define JA 8
#define JB 8

typedef unsigned long long u64;

__device__ float g_act[(size_t)NE * NT * NF];   // 16.8 MB scratch
__device__ int   g_cnt[NE];
__device__ int   g_tok[NE * NT];
__device__ float g_rw [NE * NT];

__device__ __forceinline__ u64 pk2(float lo, float hi) {
    u64 r; asm("mov.b64 %0,{%1,%2};" : "=l"(r) : "f"(lo), "f"(hi)); return r;
}
__device__ __forceinline__ void upk2(u64 v, float &lo, float &hi) {
    asm("mov.b64 {%0,%1},%2;" : "=f"(lo), "=f"(hi) : "l"(v));
}
__device__ __forceinline__ void fma2(u64 &d, u64 a, u64 b) {
    asm("fma.rn.f32x2 %0,%1,%2,%0;" : "+l"(d) : "l"(a), "l"(b));
}
__device__ __forceinline__ u64 add2(u64 a, u64 b) {
    u64 r; asm("add.rn.f32x2 %0,%1,%2;" : "=l"(r) : "l"(a), "l"(b)); return r;
}
__device__ __forceinline__ void red4(float* p, float a, float b, float c, float d) {
    asm volatile("red.global.add.v4.f32 [%0], {%1,%2,%3,%4};"
                 :: "l"(p), "f"(a), "f"(b), "f"(c), "f"(d) : "memory");
}
// Dual reduction: lane 0 ends with full sum of a, lane 16 with full sum of b.
__device__ __forceinline__ u64 reduce_pair(u64 a, u64 b, int lane) {
    u64 af = add2(a, __shfl_xor_sync(0xffffffffu, a, 16));
    u64 bf = add2(b, __shfl_xor_sync(0xffffffffu, b, 16));
    u64 m = (lane & 16) ? bf : af;
#pragma unroll
    for (int o = 8; o; o >>= 1)
        m = add2(m, __shfl_xor_sync(0xffffffffu, m, o));
    return m;
}

// ---------------------------------------------------------------------------
// Setup: block 0 builds routing tables; all blocks zero the output.
// ---------------------------------------------------------------------------
__global__ void setup_kernel(const int* __restrict__ tope,
                             const float* __restrict__ topw,
                             float* __restrict__ out)
{
    const int gid = blockIdx.x * blockDim.x + threadIdx.x;
    float4 z = make_float4(0.f, 0.f, 0.f, 0.f);
    float4* o4 = (float4*)out;
    for (int i = gid; i < (NT * NH) / 4; i += gridDim.x * blockDim.x) o4[i] = z;

    if (blockIdx.x == 0) {
        __shared__ int   se[NT * NK];
        __shared__ float sw[NT * NK];
        const int tid = threadIdx.x;
        if (tid < NT * NK) { se[tid] = tope[tid]; sw[tid] = topw[tid]; }
        __syncthreads();
        if (tid < NE) {
            const int e = tid; int c = 0;
            for (int t = 0; t < NT; t++) {
                float r = 0.f; int hit = 0;
#pragma unroll
                for (int k = 0; k < NK; k++)
                    if (se[t * NK + k] == e) { r += sw[t * NK + k]; hit = 1; }
                if (hit) { g_tok[e * NT + c] = t; g_rw[e * NT + c] = r; c++; }
            }
            g_cnt[e] = c;
        }
    }
}

// ---------------------------------------------------------------------------
// Stage A (R10 winner, verbatim): token-paired f32x2 accumulators, x staged
// pre-interleaved as (x_j0[h], x_j1[h]) u64 pairs, D=3 LDG ring, 2 CTAs/SM.
// ---------------------------------------------------------------------------
template<int JP>   // number of token pairs (1..4)
__device__ __forceinline__ void stageA_body(
    const float* __restrict__ w1, const float* __restrict__ v1,
    const u64* xq, const float* srw, int e, int fbase, int jbase, int J)
{
    const int tid = threadIdx.x, warp = tid >> 5, lane = tid & 31;
    const ulonglong2* xq2 = (const ulonglong2*)xq;

#pragma unroll 1
    for (int pass = 0; pass < 4; pass++) {
        const int f0 = fbase + pass * 16 + warp * 2;
        const ulonglong2* pwa = (const ulonglong2*)(w1 + ((size_t)e * NF + f0) * NH);
        const ulonglong2* pwb = pwa + 512;
        const ulonglong2* pva = (const ulonglong2*)(v1 + ((size_t)e * NF + f0) * NH);
        const ulonglong2* pvb = pva + 512;

        u64 aW0[JP], aW1[JP], aV0[JP], aV1[JP];
#pragma unroll
        for (int p = 0; p < JP; p++) { aW0[p] = 0ull; aW1[p] = 0ull; aV0[p] = 0ull; aV1[p] = 0ull; }

        ulonglong2 rwa[3], rwb[3], rva[3], rvb[3];
#pragma unroll
        for (int s = 0; s < 3; s++) {
            const int q = s * 32 + lane;
            rwa[s] = __ldg(pwa + q); rwb[s] = __ldg(pwb + q);
            rva[s] = __ldg(pva + q); rvb[s] = __ldg(pvb + q);
        }

#pragma unroll 3
        for (int c = 0; c < 15; c++) {
            const int sl = c % 3;
            float t0, t1, t2, t3;
            upk2(rwa[sl].x, t0, t1); upk2(rwa[sl].y, t2, t3);
            const u64 dwa0 = pk2(t0, t0), dwa1 = pk2(t1, t1), dwa2 = pk2(t2, t2), dwa3 = pk2(t3, t3);
            upk2(rwb[sl].x, t0, t1); upk2(rwb[sl].y, t2, t3);
            const u64 dwb0 = pk2(t0, t0), dwb1 = pk2(t1, t1), dwb2 = pk2(t2, t2), dwb3 = pk2(t3, t3);
            upk2(rva[sl].x, t0, t1); upk2(rva[sl].y, t2, t3);
            const u64 dva0 = pk2(t0, t0), dva1 = pk2(t1, t1), dva2 = pk2(t2, t2), dva3 = pk2(t3, t3);
            upk2(rvb[sl].x, t0, t1); upk2(rvb[sl].y, t2, t3);
            const u64 dvb0 = pk2(t0, t0), dvb1 = pk2(t1, t1), dvb2 = pk2(t2, t2), dvb3 = pk2(t3, t3);

#pragma unroll
            for (int p = 0; p < JP; p++) {
                const ulonglong2 xv0 = xq2[p * 1024 + c * 64 + lane];
                const ulonglong2 xv1 = xq2[p * 1024 + c * 64 + 32 + lane];
                fma2(aW0[p], dwa0, xv0.x); fma2(aW0[p], dwa1, xv0.y);
                fma2(aW0[p], dwa2, xv1.x); fma2(aW0[p], dwa3, xv1.y);
                fma2(aW1[p], dwb0, xv0.x); fma2(aW1[p], dwb1, xv0.y);
                fma2(aW1[p], dwb2, xv1.x); fma2(aW1[p], dwb3, xv1.y);
                fma2(aV0[p], dva0, xv0.x); fma2(aV0[p], dva1, xv0.y);
                fma2(aV0[p], dva2, xv1.x); fma2(aV0[p], dva3, xv1.y);
                fma2(aV1[p], dvb0, xv0.x); fma2(aV1[p], dvb1, xv0.y);
                fma2(aV1[p], dvb2, xv1.x); fma2(aV1[p], dvb3, xv1.y);
            }
            if (c < 13) {
                const int q = (c + 3) * 32 + lane;
                rwa[sl] = __ldg(pwa + q); rwb[sl] = __ldg(pwb + q);
                rva[sl] = __ldg(pva + q); rvb[sl] = __ldg(pvb + q);
            }
        }
        {   // final step c = 15, slot 0
            const int c = 15, sl = 0;
            float t0, t1, t2, t3;
            upk2(rwa[sl].x, t0, t1); upk2(rwa[sl].y, t2, t3);
            const u64 dwa0 = pk2(t0, t0), dwa1 = pk2(t1, t1), dwa2 = pk2(t2, t2), dwa3 = pk2(t3, t3);
            upk2(rwb[sl].x, t0, t1); upk2(rwb[sl].y, t2, t3);
            const u64 dwb0 = pk2(t0, t0), dwb1 = pk2(t1, t1), dwb2 = pk2(t2, t2), dwb3 = pk2(t3, t3);
            upk2(rva[sl].x, t0, t1); upk2(rva[sl].y, t2, t3);
            const u64 dva0 = pk2(t0, t0), dva1 = pk2(t1, t1), dva2 = pk2(t2, t2), dva3 = pk2(t3, t3);
            upk2(rvb[sl].x, t0, t1); upk2(rvb[sl].y, t2, t3);
            const u64 dvb0 = pk2(t0, t0), dvb1 = pk2(t1, t1), dvb2 = pk2(t2, t2), dvb3 = pk2(t3, t3);
#pragma unroll
            for (int p = 0; p < JP; p++) {
                const ulonglong2 xv0 = xq2[p * 1024 + c * 64 + lane];
                const ulonglong2 xv1 = xq2[p * 1024 + c * 64 + 32 + lane];
                fma2(aW0[p], dwa0, xv0.x); fma2(aW0[p], dwa1, xv0.y);
                fma2(aW0[p], dwa2, xv1.x); fma2(aW0[p], dwa3, xv1.y);
                fma2(aW1[p], dwb0, xv0.x); fma2(aW1[p], dwb1, xv0.y);
                fma2(aW1[p], dwb2, xv1.x); fma2(aW1[p], dwb3, xv1.y);
                fma2(aV0[p], dva0, xv0.x); fma2(aV0[p], dva1, xv0.y);
                fma2(aV0[p], dva2, xv1.x); fma2(aV0[p], dva3, xv1.y);
                fma2(aV1[p], dvb0, xv0.x); fma2(aV1[p], dvb1, xv0.y);
                fma2(aV1[p], dvb2, xv1.x); fma2(aV1[p], dvb3, xv1.y);
            }
        }

#pragma unroll
        for (int p = 0; p < JP; p++) {
            const u64 rg = reduce_pair(aW0[p], aW1[p], lane);
            const u64 ru = reduce_pair(aV0[p], aV1[p], lane);
            if ((lane & 15) == 0) {
                float g0, g1, u0, u1;
                upk2(rg, g0, g1); upk2(ru, u0, u1);
                const int f = f0 + (lane >> 4);
                const int j0 = 2 * p, j1 = 2 * p + 1;
                if (j0 < J) {
                    const float s = g0 / (1.f + __expf(-g0));
                    g_act[((size_t)(e * NT + jbase + j0)) * NF + f] = s * u0 * srw[j0];
                }
                if (j1 < J) {
                    const float s = g1 / (1.f + __expf(-g1));
                    g_act[((size_t)(e * NT + jbase + j1)) * NF + f] = s * u1 * srw[j1];
                }
            }
        }
    }
}

__global__ void __launch_bounds__(256, 2) stageA_kernel(
    const float* __restrict__ x, const float* __restrict__ w1, const float* __restrict__ v1)
{
    const int e = blockIdx.y;
    const int ftile = blockIdx.x >> 3, chunk = blockIdx.x & 7;
    const int jbase = chunk * JA;
    const int cnt = g_cnt[e];
    if (jbase >= cnt) return;
    const int J  = min(JA, cnt - jbase);
    const int JP = (J + 1) >> 1;

    extern __shared__ __align__(16) u64 xq[];
    __shared__ int   stok[JA];
    __shared__ float srw [JA];
    const int tid = threadIdx.x;
    if (tid < JA) {
        stok[tid] = (tid < J) ? g_tok[e * NT + jbase + tid] : 0;
        srw [tid] = (tid < J) ? g_rw [e * NT + jbase + tid] : 0.f;
    }
    __syncthreads();

    const float4* x4 = (const float4*)x;
    for (int idx = tid; idx < JP * 512; idx += 256) {
        const int jp = idx >> 9, q4 = idx & 511;
        const float4 xa = __ldg(x4 + (size_t)stok[2 * jp] * 512 + q4);
        const float4 xb = __ldg(x4 + (size_t)stok[2 * jp + 1] * 512 + q4);
        const int c = q4 >> 5, l5 = q4 & 31;
        ulonglong2* d0 = (ulonglong2*)(xq + jp * 2048 + c * 128 + l5 * 2);
        ulonglong2* d1 = (ulonglong2*)(xq + jp * 2048 + c * 128 + 64 + l5 * 2);
        *d0 = make_ulonglong2(pk2(xa.x, xb.x), pk2(xa.y, xb.y));
        *d1 = make_ulonglong2(pk2(xa.z, xb.z), pk2(xa.w, xb.w));
    }
    __syncthreads();

    const int fbase = ftile * 64;
    switch (JP) {
        case 1:  stageA_body<1>(w1, v1, xq, srw, e, fbase, jbase, J); break;
        case 2:  stageA_body<2>(w1, v1, xq, srw, e, fbase, jbase, J); break;
        case 3:  stageA_body<3>(w1, v1, xq, srw, e, fbase, jbase, J); break;
        default: stageA_body<4>(w1, v1, xq, srw, e, fbase, jbase, J); break;
    }
}

// ---------------------------------------------------------------------------
// Stage B: thread owns 4 h (2 u64 accs/j), 3 CTAs/SM (24 warps). Ring depth
// 4 on the w2 streams (8 LDG.128 in flight/warp). Weights feed FFMA2 directly
// from the ring (no dup MOVs on the weight path); act gets the pk2 dup.
// ---------------------------------------------------------------------------
template<int JT>
__device__ __forceinline__ void stageB_body(
    const float* __restrict__ w2, float* __restrict__ out,
    const float* sact, const int* stok, int e, int f0, int h0, int J)
{
    const int tid = threadIdx.x;                 // 256 threads, h = h0 + tid*4
    u64 A0[JT], A1[JT];
#pragma unroll
    for (int j = 0; j < JT; j++) { A0[j] = 0ull; A1[j] = 0ull; }

    const ulonglong2* wq = (const ulonglong2*)(w2 + ((size_t)e * NF + f0) * NH)
                           + (h0 >> 2) + tid;

    ulonglong2 Ra[4], Rb[4];                     // [slot]: rows 2s and 2s+1
#pragma unroll
    for (int s = 0; s < 4; s++) {
        Ra[s] = __ldg(wq + (size_t)(2 * s    ) * 512);
        Rb[s] = __ldg(wq + (size_t)(2 * s + 1) * 512);
    }

#pragma unroll 4
    for (int s = 0; s < 128; s++) {
        const int sl = s & 3;
#pragma unroll
        for (int j = 0; j < JT; j++) {
            const float2 a2 = *(const float2*)(sact + j * 256 + 2 * s); // LDS.64 bcast
            const u64 dx = pk2(a2.x, a2.x);
            const u64 dy = pk2(a2.y, a2.y);
            fma2(A0[j], Ra[sl].x, dx); fma2(A1[j], Ra[sl].y, dx);
            fma2(A0[j], Rb[sl].x, dy); fma2(A1[j], Rb[sl].y, dy);
        }
        if (s < 124) {
            const ulonglong2* np = wq + (size_t)(2 * (s + 4)) * 512;
            Ra[sl] = __ldg(np);
            Rb[sl] = __ldg(np + 512);
        }
    }

#pragma unroll
    for (int j = 0; j < JT; j++) {
        if (j < J) {
            float a0, a1, a2, a3;
            upk2(A0[j], a0, a1); upk2(A1[j], a2, a3);
            red4(out + (size_t)stok[j] * NH + h0 + tid * 4, a0, a1, a2, a3);
        }
    }
}

__global__ void __launch_bounds__(256, 3) stageB_kernel(
    const float* __restrict__ w2, float* __restrict__ out)
{
    const int jc = blockIdx.x, e = blockIdx.y;            // jc fastest: L2 dedup on w2
    const int fs = blockIdx.z >> 1, hh = blockIdx.z & 1;
    const int jbase = jc * JB;
    const int cnt = g_cnt[e];
    if (jbase >= cnt) return;
    const int J  = min(JB, cnt - jbase);
    const int Jp = ((J + 3) >> 2) << 2;
    const int f0 = fs * 256, h0 = hh * 1024;

    extern __shared__ __align__(16) float sact[];         // [JB][256] plain act
    __shared__ int stok[JB];
    const int tid = threadIdx.x;
    if (tid < JB) stok[tid] = (tid < J) ? g_tok[e * NT + jbase + tid] : 0;
    __syncthreads();

    for (int idx = tid; idx < Jp * 256; idx += 256) {
        const int j = idx >> 8, q = idx & 255;
        sact[idx] = (j < J)
            ? g_act[((size_t)(e * NT + jbase + j)) * NF + f0 + q] : 0.f;
    }
    __syncthreads();

    if (((J + 3) >> 2) == 1)
        stageB_body<4>(w2, out, sact, stok, e, f0, h0, J);
    else
        stageB_body<8>(w2, out, sact, stok, e, f0, h0, J);
}

// ---------------------------------------------------------------------------
extern "C" void kernel_launch(void* const* d_in, const int* in_sizes, int n_in,
                              void* d_out, int out_size)
{
    const float* x    = (const float*)d_in[0];
    const float* topw = (const float*)d_in[2];
    const int*   tope = (const int*)  d_in[3];
    const float* w1   = (const float*)d_in[4];
    const float* v1   = (const float*)d_in[5];
    const float* w2   = (const float*)d_in[6];
    float* out = (float*)d_out;

    cudaFuncSetAttribute(stageA_kernel, cudaFuncAttributeMaxDynamicSharedMemorySize, 4 * 2048 * 8);
    cudaFuncSetAttribute(stageB_kernel, cudaFuncAttributeMaxDynamicSharedMemorySize, JB * 256 * 4);

    setup_kernel<<<64, 256>>>(tope, topw, out);
    stageA_kernel<<<dim3(512, NE), 256, 4 * 2048 * 8>>>(x, w1, v1);
    stageB_kernel<<<dim3(8, NE, 32), 256, JB * 256 * 4>>>(w2, out);
}